// round 9
// baseline (speedup 1.0000x reference)
#include <cuda_runtime.h>
#include <cuda_fp16.h>
#include <cstdint>

// ---------------- problem constants ----------------
#define DFF    11008
#define MTOK   2048
#define NMOD   4096
#define KSEL   4403            // int(0.4 * 11008)
#define KP     4416            // padded to multiple of 64

// ---------------- GEMM tiling ----------------
#define BM 128
#define BN 256
#define BK 32
#define RS   40                // B smem row stride in halves (32 + 8 pad)
#define RS_A 136               // A smem row stride in halves (128 + 8 pad)
#define A_ST_BYTES (BK * RS_A * 2)       // 8704
#define B_ST_BYTES (BN * RS * 2)         // 20480
#define STG_BYTES (A_ST_BYTES + B_ST_BYTES)  // 29184
#define NSTG 6
#define GEMM_SMEM (NSTG * STG_BYTES)     // 175104
#define NCHUNK (KP / BK)       // 138

// ---------------- scratch (device globals; no allocations allowed) --------
__device__ __align__(128) __half g_xT[(long)DFF * MTOK];    // 45.1 MB (x transposed, f16)
__device__ __align__(128) __half g_wsel[(long)NMOD * KP];   // 36.2 MB
__device__ float g_partial[16 * DFF];
__device__ float g_scores[DFF];
__device__ __align__(16) int g_idx[KP];

// ---------------- PTX helpers ----------------
__device__ __forceinline__ uint32_t smem_u32(const void* p) {
    uint32_t a;
    asm("{ .reg .u64 t; cvta.to.shared.u64 t, %1; cvt.u32.u64 %0, t; }" : "=r"(a) : "l"(p));
    return a;
}
__device__ __forceinline__ void cp16(uint32_t saddr, const void* gptr) {
    unsigned long long g = (unsigned long long)__cvta_generic_to_global((void*)gptr);
    asm volatile("cp.async.cg.shared.global [%0], [%1], 16;" :: "r"(saddr), "l"(g) : "memory");
}
__device__ __forceinline__ void cp_commit() {
    asm volatile("cp.async.commit_group;" ::: "memory");
}
template <int N> __device__ __forceinline__ void cp_wait() {
    asm volatile("cp.async.wait_group %0;" :: "n"(N) : "memory");
}
__device__ __forceinline__ void ldsm4(uint32_t& r0, uint32_t& r1, uint32_t& r2, uint32_t& r3,
                                      uint32_t addr) {
    asm volatile("ldmatrix.sync.aligned.m8n8.x4.shared.b16 {%0,%1,%2,%3}, [%4];"
                 : "=r"(r0), "=r"(r1), "=r"(r2), "=r"(r3) : "r"(addr));
}
__device__ __forceinline__ void ldsm4t(uint32_t& r0, uint32_t& r1, uint32_t& r2, uint32_t& r3,
                                       uint32_t addr) {
    asm volatile("ldmatrix.sync.aligned.m8n8.x4.trans.shared.b16 {%0,%1,%2,%3}, [%4];"
                 : "=r"(r0), "=r"(r1), "=r"(r2), "=r"(r3) : "r"(addr));
}
__device__ __forceinline__ void mma16816(float* d, const uint32_t* a, const uint32_t* b) {
    asm volatile(
        "mma.sync.aligned.m16n8k16.row.col.f32.f16.f16.f32 "
        "{%0,%1,%2,%3}, {%4,%5,%6,%7}, {%8,%9}, {%0,%1,%2,%3};"
        : "+f"(d[0]), "+f"(d[1]), "+f"(d[2]), "+f"(d[3])
        : "r"(a[0]), "r"(a[1]), "r"(a[2]), "r"(a[3]), "r"(b[0]), "r"(b[1]));
}

// ================= kernel 1: partial column scores + xT f16 emit ============
// grid (43, 16), block 256. Also writes g_xT[j][rb*128 .. +127] (f16 pairs).
__global__ void __launch_bounds__(256) score_partial_kernel(const float* __restrict__ x) {
    int j = blockIdx.x * 256 + threadIdx.x;       // 43*256 == 11008 exactly
    int rb = blockIdx.y;
    const float* xp = x + (long)rb * 128 * DFF + j;
    float s = 0.f;
    uint32_t pk[64];
    #pragma unroll
    for (int r2 = 0; r2 < 64; r2++) {
        float v0 = xp[(long)(2 * r2) * DFF];
        float v1 = xp[(long)(2 * r2 + 1) * DFF];
        s += fmaxf(v0, 0.f) + fmaxf(v1, 0.f);
        __half2 h2 = __floats2half2_rn(v0, v1);   // low = token 2*r2
        pk[r2] = *reinterpret_cast<uint32_t*>(&h2);
    }
    g_partial[rb * DFF + j] = s;
    uint4* dst = (uint4*)(g_xT + (long)j * MTOK + rb * 128);
    #pragma unroll
    for (int q = 0; q < 16; q++)
        dst[q] = make_uint4(pk[4 * q], pk[4 * q + 1], pk[4 * q + 2], pk[4 * q + 3]);
}

// ================= kernel 2: reduce + radix top-K select + compaction =======
__global__ void select_kernel() {
    __shared__ unsigned int hist[256];
    __shared__ int s_gt[1024], s_eq[1024];
    __shared__ unsigned int s_pfx;
    __shared__ int s_rem;
    int tid = threadIdx.x;

    for (int j = tid; j < DFF; j += 1024) {
        float s = 0.f;
        #pragma unroll
        for (int p = 0; p < 16; p++) s += g_partial[p * DFF + j];
        g_scores[j] = s;
    }
    // zero idx padding (pad rows read xT row 0; annihilated by zero B pad)
    if (tid >= 1024 - (KP - KSEL)) g_idx[KSEL + tid - (1024 - (KP - KSEL))] = 0;
    __syncthreads();
    if (tid == 0) { s_pfx = 0u; s_rem = KSEL; }
    __syncthreads();

    // 4-pass MSB radix select: scores >= 0 so float bits are uint-monotonic
    for (int shift = 24; shift >= 0; shift -= 8) {
        if (tid < 256) hist[tid] = 0u;
        __syncthreads();
        unsigned int pfx = s_pfx;
        for (int j = tid; j < DFF; j += 1024) {
            unsigned int b = __float_as_uint(g_scores[j]);
            bool cand = (shift == 24) || ((b >> (shift + 8)) == pfx);
            if (cand) atomicAdd(&hist[(b >> shift) & 255u], 1u);
        }
        __syncthreads();
        if (tid == 0) {
            int rem = s_rem;
            unsigned int cum = 0; int d;
            for (d = 255; d >= 0; d--) {
                if (cum + hist[d] >= (unsigned)rem) break;
                cum += hist[d];
            }
            s_rem = rem - (int)cum;
            s_pfx = (s_pfx << 8) | (unsigned)d;
        }
        __syncthreads();
    }
    unsigned int T = s_pfx;
    int rem = s_rem;                   // ties at exact threshold to include

    // deterministic ordered compaction: contiguous ranges of 11 cols/thread
    int j0 = tid * 11;
    int j1 = j0 + 11; if (j1 > DFF) j1 = DFF; if (j0 > DFF) j0 = DFF;
    int gt = 0, eq = 0;
    for (int j = j0; j < j1; j++) {
        unsigned int b = __float_as_uint(g_scores[j]);
        if (b > T) gt++; else if (b == T) eq++;
    }
    s_gt[tid] = gt; s_eq[tid] = eq;
    __syncthreads();
    for (int off = 1; off < 1024; off <<= 1) {
        int vg = (tid >= off) ? s_gt[tid - off] : 0;
        int ve = (tid >= off) ? s_eq[tid - off] : 0;
        __syncthreads();
        s_gt[tid] += vg; s_eq[tid] += ve;
        __syncthreads();
    }
    int gt_base = s_gt[tid] - gt;
    int eq_base = s_eq[tid] - eq;
    int total_gt = s_gt[1023];
    int pg = gt_base, pe = eq_base;
    for (int j = j0; j < j1; j++) {
        unsigned int b = __float_as_uint(g_scores[j]);
        if (b > T) { g_idx[pg++] = j; }
        else if (b == T) { if (pe < rem) g_idx[total_gt + pe] = j; pe++; }
    }
}

// ================= kernel 3: W row-staged gather =================
__global__ void __launch_bounds__(512) gather_w_kernel(const float* __restrict__ W) {
    extern __shared__ float srow[];   // DFF floats = 44032 B
    int b = blockIdx.x;
    const float* src = W + (long)b * DFF;
    __half* dst = g_wsel + (long)b * KP;

    uint32_t sbase = smem_u32(srow);
    #pragma unroll
    for (int i = 0; i < 6; i++) {
        int seg = threadIdx.x + i * 512;
        if (seg < DFF / 4) cp16(sbase + seg * 16, src + seg * 4);
    }
    cp_commit();
    cp_wait<0>();
    __syncthreads();

    const int2* idx2 = (const int2*)g_idx;
    __half2* d2 = (__half2*)dst;
    for (int p = threadIdx.x; p < KP / 2; p += 512) {
        int k0 = p * 2;
        float v0 = 0.f, v1 = 0.f;
        if (k0 < KSEL) {
            int2 ii = __ldg(&idx2[p]);
            v0 = srow[ii.x];
            if (k0 + 1 < KSEL) v1 = srow[ii.y];
        }
        d2[p] = __floats2half2_rn(v0, v1);
    }
}

// ================= kernel 4: HMMA f16 GEMM (A direct from xT) ===============
__device__ __forceinline__ void load_stage(uint32_t stb, int chunk, int bmBase, int bnBase, int tid) {
    long c0 = (long)chunk * BK;          // in halves
    // A: 32 k-rows, each = xT[idx[c0+kk]][bmBase..+127] (256B contiguous)
    int kk = tid >> 3, seg = tid & 7;
    long rowA = __ldg(&g_idx[c0 + kk]);
    const __half* srcA = g_xT + rowA * MTOK + bmBase;
    uint32_t abase = stb + (uint32_t)(kk * RS_A * 2);
    cp16(abase + seg * 16, srcA + seg * 8);
    cp16(abase + (seg + 8) * 16, srcA + (seg + 8) * 8);
    // B: 256 d_model rows (K-major, as before)
    int row = tid >> 2, sg = tid & 3;
    #pragma unroll
    for (int i = 0; i < 4; i++) {
        int r = row + i * 64;
        cp16(stb + (uint32_t)(A_ST_BYTES + r * RS * 2 + sg * 16),
             &g_wsel[(long)(bnBase + r) * KP + c0 + sg * 8]);
    }
}

__device__ __forceinline__ void ldsm_half(uint32_t stb, int h,
                                          const uint32_t* a_off, const uint32_t* b_off,
                                          uint32_t (*A)[4], uint32_t (*B)[4]) {
    #pragma unroll
    for (int mt = 0; mt < 4; mt++)
        ldsm4t(A[mt][0], A[mt][1], A[mt][2], A[mt][3],
               stb + a_off[mt] + h * (16 * RS_A * 2));
    #pragma unroll
    for (int p = 0; p < 4; p++)
        ldsm4(B[p][0], B[p][1], B[p][2], B[p][3], stb + b_off[p] + h * 32);
}

__device__ __forceinline__ void mma_half(float (*acc)[8][4],
                                         uint32_t (*A)[4], uint32_t (*B)[4]) {
    #pragma unroll
    for (int mt = 0; mt < 4; mt++)
        #pragma unroll
        for (int nt = 0; nt < 8; nt++)
            mma16816(acc[mt][nt], A[mt], &B[nt >> 1][(nt & 1) * 2]);
}

__global__ void __launch_bounds__(256, 1) gemm_kernel(float* __restrict__ out) {
    extern __shared__ char smem[];
    uint32_t sb = smem_u32(smem);
    int tid = threadIdx.x, wid = tid >> 5, lane = tid & 31;
    int bmBase = blockIdx.y * BM, bnBase = blockIdx.x * BN;
    int wm = (wid >> 2) * 64;            // warp M base within tile
    int wn = (wid & 3) * 64;             // warp N base within tile

    // A (trans) per-lane offsets: source tile rows are k, cols are m.
    // group g = lane>>3, i = lane&7:
    //   g0: (k0-7,  m0-7)  g1: (k0-7,  m8-15)  g2: (k8-15, m0-7)  g3: (k8-15, m8-15)
    int g = lane >> 3, i8 = lane & 7;
    int krow = ((g >> 1) ? 8 : 0) + i8;
    uint32_t a_off[4], b_off[4];
    #pragma unroll
    for (int mt = 0; mt < 4; mt++) {
        int mcol = wm + mt * 16 + (g & 1) * 8;
        a_off[mt] = (uint32_t)((krow * RS_A + mcol) * 2);
    }
    int quad = lane >> 3, r8 = lane & 7;
    #pragma unroll
    for (int p = 0; p < 4; p++) {
        int row = wn + p * 16 + (quad >> 1) * 8 + r8;
        int col = (quad & 1) * 8;
        b_off[p] = (uint32_t)(A_ST_BYTES + (row * RS + col) * 2);
    }

    float acc[4][8][4];
    #pragma unroll
    for (int mt = 0; mt < 4; mt++)
        #pragma unroll
        for (int nt = 0; nt < 8; nt++)
            #pragma unroll
            for (int q = 0; q < 4; q++) acc[mt][nt][q] = 0.f;

    // preload NSTG-1 = 5 stages
    #pragma unroll
    for (int s = 0; s < NSTG - 1; s++) {
        load_stage(sb + s * STG_BYTES, s, bmBase, bnBase, tid);
        cp_commit();
    }

    uint32_t A0[4][4], B0[4][4], A1[4][4], B1[4][4];
    cp_wait<NSTG - 2>();
    __syncthreads();
    ldsm_half(sb, 0, a_off, b_off, A0, B0);      // chunk 0, half 0

    int st = 0;
    #pragma unroll 1
    for (int c = 0; c < NCHUNK; c++) {
        uint32_t stb = sb + st * STG_BYTES;
        // prefetch half 1 of current chunk before running half-0 MMAs
        ldsm_half(stb, 1, a_off, b_off, A1, B1);
        if (c + NSTG - 1 < NCHUNK) {
            int stn = st + (NSTG - 1); if (stn >= NSTG) stn -= NSTG;
            load_stage(sb + stn * STG_BYTES, c + NSTG - 1, bmBase, bnBase, tid);
        }
        cp_commit();
        mma_half(acc, A0, B0);

        cp_wait<NSTG - 2>();          // stage c+1 resident
        __syncthreads();
        int stn = st + 1; if (stn == NSTG) stn = 0;
        // prefetch half 0 of next chunk before running half-1 MMAs
        if (c + 1 < NCHUNK) ldsm_half(sb + stn * STG_BYTES, 0, a_off, b_off, A0, B0);
        mma_half(acc, A1, B1);
        st = stn;
    }

    // epilogue: direct f32 stores
    int rq = lane >> 2, cq = lane & 3;
    #pragma unroll
    for (int mt = 0; mt < 4; mt++) {
        #pragma unroll
        for (int nt = 0; nt < 8; nt++) {
            int m0 = bmBase + wm + mt * 16 + rq;
            int n0 = bnBase + wn + nt * 8 + cq * 2;
            float2* p0 = (float2*)(out + (long)m0 * NMOD + n0);
            float2* p1 = (float2*)(out + (long)(m0 + 8) * NMOD + n0);
            *p0 = make_float2(acc[mt][nt][0], acc[mt][nt][1]);
            *p1 = make_float2(acc[mt][nt][2], acc[mt][nt][3]);
        }
    }
}

// ================= launch =================
extern "C" void kernel_launch(void* const* d_in, const int* in_sizes, int n_in,
                              void* d_out, int out_size) {
    const float* x = (const float*)d_in[0];   // [1, 2048, 11008] f32
    const float* W = (const float*)d_in[1];   // [4096, 11008] f32
    float* out = (float*)d_out;               // [1, 2048, 4096] f32

    cudaFuncSetAttribute(gemm_kernel, cudaFuncAttributeMaxDynamicSharedMemorySize, GEMM_SMEM);
    cudaFuncSetAttribute(gather_w_kernel, cudaFuncAttributeMaxDynamicSharedMemorySize, DFF * 4);

    score_partial_kernel<<<dim3(43, 16), 256>>>(x);
    select_kernel<<<1, 1024>>>();
    gather_w_kernel<<<NMOD, 512, DFF * 4>>>(W);
    gemm_kernel<<<dim3(NMOD / BN, MTOK / BM), 256, GEMM_SMEM>>>(out);
}

// round 10
// speedup vs baseline: 1.1479x; 1.1479x over previous
#include <cuda_runtime.h>
#include <cuda_fp16.h>
#include <cstdint>

// ---------------- problem constants ----------------
#define DFF    11008
#define MTOK   2048
#define NMOD   4096
#define KSEL   4403            // int(0.4 * 11008)
#define KP     4416            // padded to multiple of 64

// ---------------- GEMM tiling (R7-exact) ----------------
#define BM 128
#define BN 256
#define BK 32
#define RS 40                  // smem row stride in halves (32 + 8 pad)
#define A_BYTES (BM * RS * 2)  // 10240
#define B_BYTES (BN * RS * 2)  // 20480
#define STG_BYTES (A_BYTES + B_BYTES)  // 30720
#define NSTG 6
#define GEMM_SMEM (NSTG * STG_BYTES)   // 184320
#define NCHUNK (KP / BK)       // 138

// ---------------- scratch (device globals; no allocations allowed) --------
__device__ __align__(128) __half g_xT[(long)DFF * MTOK];    // 45.1 MB (x^T, f16)
__device__ __align__(128) __half g_xsel[(long)MTOK * KP];   // 18.1 MB
__device__ __align__(128) __half g_wsel[(long)NMOD * KP];   // 36.2 MB
__device__ float g_partial[16 * DFF];
__device__ float g_scores[DFF];
__device__ __align__(16) int g_idx[KP];

// ---------------- PTX helpers ----------------
__device__ __forceinline__ uint32_t smem_u32(const void* p) {
    uint32_t a;
    asm("{ .reg .u64 t; cvta.to.shared.u64 t, %1; cvt.u32.u64 %0, t; }" : "=r"(a) : "l"(p));
    return a;
}
__device__ __forceinline__ void cp16(uint32_t saddr, const void* gptr) {
    unsigned long long g = (unsigned long long)__cvta_generic_to_global((void*)gptr);
    asm volatile("cp.async.cg.shared.global [%0], [%1], 16;" :: "r"(saddr), "l"(g) : "memory");
}
__device__ __forceinline__ void cp_commit() {
    asm volatile("cp.async.commit_group;" ::: "memory");
}
template <int N> __device__ __forceinline__ void cp_wait() {
    asm volatile("cp.async.wait_group %0;" :: "n"(N) : "memory");
}
__device__ __forceinline__ void ldsm4(uint32_t& r0, uint32_t& r1, uint32_t& r2, uint32_t& r3,
                                      uint32_t addr) {
    asm volatile("ldmatrix.sync.aligned.m8n8.x4.shared.b16 {%0,%1,%2,%3}, [%4];"
                 : "=r"(r0), "=r"(r1), "=r"(r2), "=r"(r3) : "r"(addr));
}
__device__ __forceinline__ void mma16816(float* d, const uint32_t* a, const uint32_t* b) {
    asm volatile(
        "mma.sync.aligned.m16n8k16.row.col.f32.f16.f16.f32 "
        "{%0,%1,%2,%3}, {%4,%5,%6,%7}, {%8,%9}, {%0,%1,%2,%3};"
        : "+f"(d[0]), "+f"(d[1]), "+f"(d[2]), "+f"(d[3])
        : "r"(a[0]), "r"(a[1]), "r"(a[2]), "r"(a[3]), "r"(b[0]), "r"(b[1]));
}

// ================= kernel 1: partial column scores + xT f16 emit ============
__global__ void __launch_bounds__(256) score_partial_kernel(const float* __restrict__ x) {
    int j = blockIdx.x * 256 + threadIdx.x;       // 43*256 == 11008 exactly
    int rb = blockIdx.y;
    const float* xp = x + (long)rb * 128 * DFF + j;
    float s = 0.f;
    uint32_t pk[64];
    #pragma unroll
    for (int r2 = 0; r2 < 64; r2++) {
        float v0 = xp[(long)(2 * r2) * DFF];
        float v1 = xp[(long)(2 * r2 + 1) * DFF];
        s += fmaxf(v0, 0.f) + fmaxf(v1, 0.f);
        __half2 h2 = __floats2half2_rn(v0, v1);   // low half = token 2*r2
        pk[r2] = *reinterpret_cast<uint32_t*>(&h2);
    }
    g_partial[rb * DFF + j] = s;
    uint4* dst = (uint4*)(g_xT + (long)j * MTOK + rb * 128);
    #pragma unroll
    for (int q = 0; q < 16; q++)
        dst[q] = make_uint4(pk[4 * q], pk[4 * q + 1], pk[4 * q + 2], pk[4 * q + 3]);
}

// ================= kernel 2: reduce + radix top-K select + compaction =======
__global__ void select_kernel() {
    __shared__ unsigned int hist[256];
    __shared__ int s_gt[1024], s_eq[1024];
    __shared__ unsigned int s_pfx;
    __shared__ int s_rem;
    int tid = threadIdx.x;

    for (int j = tid; j < DFF; j += 1024) {
        float s = 0.f;
        #pragma unroll
        for (int p = 0; p < 16; p++) s += g_partial[p * DFF + j];
        g_scores[j] = s;
    }
    // zero idx padding (pad rows read xT row 0; annihilated by zero B pad)
    if (tid >= 1024 - (KP - KSEL)) g_idx[KSEL + tid - (1024 - (KP - KSEL))] = 0;
    __syncthreads();
    if (tid == 0) { s_pfx = 0u; s_rem = KSEL; }
    __syncthreads();

    // 4-pass MSB radix select: scores >= 0 so float bits are uint-monotonic
    for (int shift = 24; shift >= 0; shift -= 8) {
        if (tid < 256) hist[tid] = 0u;
        __syncthreads();
        unsigned int pfx = s_pfx;
        for (int j = tid; j < DFF; j += 1024) {
            unsigned int b = __float_as_uint(g_scores[j]);
            bool cand = (shift == 24) || ((b >> (shift + 8)) == pfx);
            if (cand) atomicAdd(&hist[(b >> shift) & 255u], 1u);
        }
        __syncthreads();
        if (tid == 0) {
            int rem = s_rem;
            unsigned int cum = 0; int d;
            for (d = 255; d >= 0; d--) {
                if (cum + hist[d] >= (unsigned)rem) break;
                cum += hist[d];
            }
            s_rem = rem - (int)cum;
            s_pfx = (s_pfx << 8) | (unsigned)d;
        }
        __syncthreads();
    }
    unsigned int T = s_pfx;
    int rem = s_rem;                   // ties at exact threshold to include

    // deterministic ordered compaction: contiguous ranges of 11 cols/thread
    int j0 = tid * 11;
    int j1 = j0 + 11; if (j1 > DFF) j1 = DFF; if (j0 > DFF) j0 = DFF;
    int gt = 0, eq = 0;
    for (int j = j0; j < j1; j++) {
        unsigned int b = __float_as_uint(g_scores[j]);
        if (b > T) gt++; else if (b == T) eq++;
    }
    s_gt[tid] = gt; s_eq[tid] = eq;
    __syncthreads();
    for (int off = 1; off < 1024; off <<= 1) {
        int vg = (tid >= off) ? s_gt[tid - off] : 0;
        int ve = (tid >= off) ? s_eq[tid - off] : 0;
        __syncthreads();
        s_gt[tid] += vg; s_eq[tid] += ve;
        __syncthreads();
    }
    int gt_base = s_gt[tid] - gt;
    int eq_base = s_eq[tid] - eq;
    int total_gt = s_gt[1023];
    int pg = gt_base, pe = eq_base;
    for (int j = j0; j < j1; j++) {
        unsigned int b = __float_as_uint(g_scores[j]);
        if (b > T) { g_idx[pg++] = j; }
        else if (b == T) { if (pe < rem) g_idx[total_gt + pe] = j; pe++; }
    }
}

// ================= kernel 3: x transpose-gather  xT[idx[kk]] -> g_xsel ======
// grid (KP/64=69, MTOK/128=16), 256 threads. 64 kk-rows x 128 tokens per tile.
#define TX_RS 136   // smem row stride in halves (128 + 8); 272B, 16B-aligned
__global__ void __launch_bounds__(256) tx_kernel() {
    __shared__ __half stile[64 * TX_RS];
    int kk0 = blockIdx.x * 64, tok0 = blockIdx.y * 128;
    int tid = threadIdx.x;
    uint32_t sbase = smem_u32(stile);

    // load: 64 rows x 256B; 4 threads/row, 4 cp16 each
    int kk = tid >> 2, sq = tid & 3;
    long rowA = __ldg(&g_idx[kk0 + kk]);
    const __half* src = g_xT + rowA * MTOK + tok0;
    uint32_t rb = sbase + (uint32_t)(kk * TX_RS * 2);
    #pragma unroll
    for (int i = 0; i < 4; i++)
        cp16(rb + (sq + 4 * i) * 16, src + (sq + 4 * i) * 8);
    cp_commit();
    cp_wait<0>();
    __syncthreads();

    // store: thread -> token row (tok0 + t), kk half hf (32 halves = 64B)
    int t = tid & 127, hf = tid >> 7;
    int kkb = hf * 32;
    uint32_t pk[16];
    #pragma unroll
    for (int i = 0; i < 16; i++) {
        __half lo = stile[(kkb + 2 * i) * TX_RS + t];
        __half hi = stile[(kkb + 2 * i + 1) * TX_RS + t];
        __half2 h2 = __halves2half2(lo, hi);
        pk[i] = *reinterpret_cast<uint32_t*>(&h2);
    }
    uint4* dst = (uint4*)(g_xsel + (long)(tok0 + t) * KP + kk0 + kkb);
    #pragma unroll
    for (int q = 0; q < 4; q++)
        dst[q] = make_uint4(pk[4 * q], pk[4 * q + 1], pk[4 * q + 2], pk[4 * q + 3]);
}

// ================= kernel 4: W row-staged gather =================
__global__ void __launch_bounds__(512) gather_w_kernel(const float* __restrict__ W) {
    extern __shared__ float srow[];   // DFF floats = 44032 B
    int b = blockIdx.x;
    const float* src = W + (long)b * DFF;
    __half* dst = g_wsel + (long)b * KP;

    uint32_t sbase = smem_u32(srow);
    #pragma unroll
    for (int i = 0; i < 6; i++) {
        int seg = threadIdx.x + i * 512;
        if (seg < DFF / 4) cp16(sbase + seg * 16, src + seg * 4);
    }
    cp_commit();
    cp_wait<0>();
    __syncthreads();

    const int2* idx2 = (const int2*)g_idx;
    __half2* d2 = (__half2*)dst;
    for (int p = threadIdx.x; p < KP / 2; p += 512) {
        int k0 = p * 2;
        float v0 = 0.f, v1 = 0.f;
        if (k0 < KSEL) {
            int2 ii = __ldg(&idx2[p]);
            v0 = srow[ii.x];
            if (k0 + 1 < KSEL) v1 = srow[ii.y];
        }
        d2[p] = __floats2half2_rn(v0, v1);
    }
}

// ================= kernel 5: HMMA f16 GEMM (R7-exact) =======================
__device__ __forceinline__ void load_stage(uint32_t stb, int chunk, int bmBase, int bnBase, int tid) {
    long c0 = (long)chunk * BK;          // in halves
    int row = tid >> 2, seg = tid & 3;   // row 0..63, seg 0..3 (16B segments)
    #pragma unroll
    for (int i = 0; i < 2; i++) {        // A: 128 token rows
        int r = row + i * 64;
        cp16(stb + (uint32_t)(r * RS * 2 + seg * 16),
             &g_xsel[(long)(bmBase + r) * KP + c0 + seg * 8]);
    }
    #pragma unroll
    for (int i = 0; i < 4; i++) {        // B: 256 d_model rows
        int r = row + i * 64;
        cp16(stb + (uint32_t)(A_BYTES + r * RS * 2 + seg * 16),
             &g_wsel[(long)(bnBase + r) * KP + c0 + seg * 8]);
    }
}

__device__ __forceinline__ void ldsm_half(uint32_t stb, int h,
                                          const uint32_t* a_off, const uint32_t* b_off,
                                          uint32_t (*A)[4], uint32_t (*B)[4]) {
    #pragma unroll
    for (int mt = 0; mt < 4; mt++)
        ldsm4(A[mt][0], A[mt][1], A[mt][2], A[mt][3], stb + a_off[mt] + h * 32);
    #pragma unroll
    for (int p = 0; p < 4; p++)
        ldsm4(B[p][0], B[p][1], B[p][2], B[p][3], stb + b_off[p] + h * 32);
}

__device__ __forceinline__ void mma_half(float (*acc)[8][4],
                                         uint32_t (*A)[4], uint32_t (*B)[4]) {
    #pragma unroll
    for (int mt = 0; mt < 4; mt++)
        #pragma unroll
        for (int nt = 0; nt < 8; nt++)
            mma16816(acc[mt][nt], A[mt], &B[nt >> 1][(nt & 1) * 2]);
}

__global__ void __launch_bounds__(256, 1) gemm_kernel(float* __restrict__ out) {
    extern __shared__ char smem[];
    uint32_t sb = smem_u32(smem);
    int tid = threadIdx.x, wid = tid >> 5, lane = tid & 31;
    int bmBase = blockIdx.y * BM, bnBase = blockIdx.x * BN;
    int wm = (wid >> 2) * 64;            // warp M base within tile
    int wn = (wid & 3) * 64;             // warp N base within tile

    int quad = lane >> 3, r8 = lane & 7;
    uint32_t a_off[4], b_off[4];
    #pragma unroll
    for (int mt = 0; mt < 4; mt++) {
        int row = wm + mt * 16 + (quad & 1) * 8 + r8;
        int col = (quad >> 1) * 8;
        a_off[mt] = (uint32_t)((row * RS + col) * 2);
    }
    #pragma unroll
    for (int p = 0; p < 4; p++) {
        int row = wn + p * 16 + (quad >> 1) * 8 + r8;
        int col = (quad & 1) * 8;
        b_off[p] = (uint32_t)(A_BYTES + (row * RS + col) * 2);
    }

    float acc[4][8][4];
    #pragma unroll
    for (int mt = 0; mt < 4; mt++)
        #pragma unroll
        for (int nt = 0; nt < 8; nt++)
            #pragma unroll
            for (int q = 0; q < 4; q++) acc[mt][nt][q] = 0.f;

    // preload NSTG-1 = 5 stages
    #pragma unroll
    for (int s = 0; s < NSTG - 1; s++) {
        load_stage(sb + s * STG_BYTES, s, bmBase, bnBase, tid);
        cp_commit();
    }

    uint32_t A0[4][4], B0[4][4], A1[4][4], B1[4][4];
    cp_wait<NSTG - 2>();
    __syncthreads();
    ldsm_half(sb, 0, a_off, b_off, A0, B0);      // chunk 0, half 0

    int st = 0;
    #pragma unroll 1
    for (int c = 0; c < NCHUNK; c++) {
        uint32_t stb = sb + st * STG_BYTES;
        // prefetch half 1 of current chunk before running half-0 MMAs
        ldsm_half(stb, 1, a_off, b_off, A1, B1);
        if (c + NSTG - 1 < NCHUNK) {
            int stn = st + (NSTG - 1); if (stn >= NSTG) stn -= NSTG;
            load_stage(sb + stn * STG_BYTES, c + NSTG - 1, bmBase, bnBase, tid);
        }
        cp_commit();
        mma_half(acc, A0, B0);

        cp_wait<NSTG - 2>();          // stage c+1 resident
        __syncthreads();
        int stn = st + 1; if (stn == NSTG) stn = 0;
        // prefetch half 0 of next chunk before running half-1 MMAs
        if (c + 1 < NCHUNK) ldsm_half(sb + stn * STG_BYTES, 0, a_off, b_off, A0, B0);
        mma_half(acc, A1, B1);
        st = stn;
    }

    // epilogue: direct f32 stores
    int rq = lane >> 2, cq = lane & 3;
    #pragma unroll
    for (int mt = 0; mt < 4; mt++) {
        #pragma unroll
        for (int nt = 0; nt < 8; nt++) {
            int m0 = bmBase + wm + mt * 16 + rq;
            int n0 = bnBase + wn + nt * 8 + cq * 2;
            float2* p0 = (float2*)(out + (long)m0 * NMOD + n0);
            float2* p1 = (float2*)(out + (long)(m0 + 8) * NMOD + n0);
            *p0 = make_float2(acc[mt][nt][0], acc[mt][nt][1]);
            *p1 = make_float2(acc[mt][nt][2], acc[mt][nt][3]);
        }
    }
}

// ================= launch =================
extern "C" void kernel_launch(void* const* d_in, const int* in_sizes, int n_in,
                              void* d_out, int out_size) {
    const float* x = (const float*)d_in[0];   // [1, 2048, 11008] f32
    const float* W = (const float*)d_in[1];   // [4096, 11008] f32
    float* out = (float*)d_out;               // [1, 2048, 4096] f32

    cudaFuncSetAttribute(gemm_kernel, cudaFuncAttributeMaxDynamicSharedMemorySize, GEMM_SMEM);
    cudaFuncSetAttribute(gather_w_kernel, cudaFuncAttributeMaxDynamicSharedMemorySize, DFF * 4);

    score_partial_kernel<<<dim3(43, 16), 256>>>(x);
    select_kernel<<<1, 1024>>>();
    tx_kernel<<<dim3(KP / 64, MTOK / 128), 256>>>();
    gather_w_kernel<<<NMOD, 512, DFF * 4>>>(W);
    gemm_kernel<<<dim3(NMOD / BN, MTOK / BM), 256, GEMM_SMEM>>>(out);
}

// round 13
// speedup vs baseline: 1.2161x; 1.0595x over previous
#include <cuda_runtime.h>
#include <cuda_fp16.h>
#include <cstdint>

// ---------------- problem constants ----------------
#define DFF    11008
#define MTOK   2048
#define NMOD   4096
#define KSEL   4403            // int(0.4 * 11008)
#define KP     4416            // padded to multiple of 64

// ---------------- GEMM tiling (R7-exact) ----------------
#define BM 128
#define BN 256
#define BK 32
#define RS 40                  // smem row stride in halves (32 + 8 pad)
#define A_BYTES (BM * RS * 2)  // 10240
#define B_BYTES (BN * RS * 2)  // 20480
#define STG_BYTES (A_BYTES + B_BYTES)  // 30720
#define NSTG 6
#define GEMM_SMEM (NSTG * STG_BYTES)   // 184320
#define NCHUNK (KP / BK)       // 138

// ---------------- scratch (device globals; no allocations allowed) --------
__device__ __align__(128) __half g_xsel[(long)MTOK * KP];   // 18.1 MB
__device__ __align__(128) __half g_wsel[(long)NMOD * KP];   // 36.2 MB
__device__ float g_partial[16 * DFF];
__device__ __align__(16) float g_scores[DFF];
__device__ __align__(16) int g_idx[KP];

// ---------------- PTX helpers ----------------
__device__ __forceinline__ uint32_t smem_u32(const void* p) {
    uint32_t a;
    asm("{ .reg .u64 t; cvta.to.shared.u64 t, %1; cvt.u32.u64 %0, t; }" : "=r"(a) : "l"(p));
    return a;
}
__device__ __forceinline__ void cp16(uint32_t saddr, const void* gptr) {
    unsigned long long g = (unsigned long long)__cvta_generic_to_global((void*)gptr);
    asm volatile("cp.async.cg.shared.global [%0], [%1], 16;" :: "r"(saddr), "l"(g) : "memory");
}
__device__ __forceinline__ void cp_commit() {
    asm volatile("cp.async.commit_group;" ::: "memory");
}
template <int N> __device__ __forceinline__ void cp_wait() {
    asm volatile("cp.async.wait_group %0;" :: "n"(N) : "memory");
}
__device__ __forceinline__ void ldsm4(uint32_t& r0, uint32_t& r1, uint32_t& r2, uint32_t& r3,
                                      uint32_t addr) {
    asm volatile("ldmatrix.sync.aligned.m8n8.x4.shared.b16 {%0,%1,%2,%3}, [%4];"
                 : "=r"(r0), "=r"(r1), "=r"(r2), "=r"(r3) : "r"(addr));
}
__device__ __forceinline__ void mma16816(float* d, const uint32_t* a, const uint32_t* b) {
    asm volatile(
        "mma.sync.aligned.m16n8k16.row.col.f32.f16.f16.f32 "
        "{%0,%1,%2,%3}, {%4,%5,%6,%7}, {%8,%9}, {%0,%1,%2,%3};"
        : "+f"(d[0]), "+f"(d[1]), "+f"(d[2]), "+f"(d[3])
        : "r"(a[0]), "r"(a[1]), "r"(a[2]), "r"(a[3]), "r"(b[0]), "r"(b[1]));
}

// ================= kernel 1: partial column scores =================
__global__ void score_partial_kernel(const float* __restrict__ x) {
    int j = blockIdx.x * 256 + threadIdx.x;       // 43*256 == 11008 exactly
    int rb = blockIdx.y;
    const float* xp = x + (long)rb * 128 * DFF + j;
    float s = 0.f;
    #pragma unroll 4
    for (int r = 0; r < 128; r++) s += fmaxf(xp[(long)r * DFF], 0.f);
    g_partial[rb * DFF + j] = s;
}

// ================= kernel 1b: chip-wide partial reduce =================
__global__ void reduce_scores_kernel() {
    int j = blockIdx.x * 256 + threadIdx.x;       // 43*256 == 11008
    float s = 0.f;
    #pragma unroll
    for (int p = 0; p < 16; p++) s += g_partial[p * DFF + j];
    g_scores[j] = s;
}

// ================= kernel 2: radix top-K select (smem-resident scores) ======
__global__ void select_kernel() {
    extern __shared__ float ssc[];    // DFF floats = 44032 B (dynamic)
    __shared__ unsigned int hist[256];
    __shared__ int s_gt[1024], s_eq[1024];
    __shared__ unsigned int s_pfx;
    __shared__ int s_rem;
    int tid = threadIdx.x;

    // stage scores into smem once (cp.async, 2752 x 16B)
    uint32_t sbase = smem_u32(ssc);
    #pragma unroll
    for (int i = 0; i < 3; i++) {
        int seg = tid + i * 1024;
        if (seg < DFF / 4) cp16(sbase + seg * 16, g_scores + seg * 4);
    }
    cp_commit();
    // zero idx padding (pad entries point at column 0; B pad columns are zero)
    if (tid >= 1024 - (KP - KSEL)) g_idx[KSEL + tid - (1024 - (KP - KSEL))] = 0;
    if (tid == 0) { s_pfx = 0u; s_rem = KSEL; }
    cp_wait<0>();
    __syncthreads();

    // 4-pass MSB radix select: scores >= 0 so float bits are uint-monotonic
    for (int shift = 24; shift >= 0; shift -= 8) {
        if (tid < 256) hist[tid] = 0u;
        __syncthreads();
        unsigned int pfx = s_pfx;
        #pragma unroll 2
        for (int j = tid; j < DFF; j += 1024) {
            unsigned int b = __float_as_uint(ssc[j]);
            bool cand = (shift == 24) || ((b >> (shift + 8)) == pfx);
            if (cand) atomicAdd(&hist[(b >> shift) & 255u], 1u);
        }
        __syncthreads();
        if (tid == 0) {
            int rem = s_rem;
            unsigned int cum = 0; int d;
            for (d = 255; d >= 0; d--) {
                if (cum + hist[d] >= (unsigned)rem) break;
                cum += hist[d];
            }
            s_rem = rem - (int)cum;
            s_pfx = (s_pfx << 8) | (unsigned)d;
        }
        __syncthreads();
    }
    unsigned int T = s_pfx;
    int rem = s_rem;                   // ties at exact threshold to include

    // deterministic ordered compaction: contiguous ranges of 11 cols/thread
    int j0 = tid * 11;
    int j1 = j0 + 11; if (j1 > DFF) j1 = DFF; if (j0 > DFF) j0 = DFF;
    int gt = 0, eq = 0;
    for (int j = j0; j < j1; j++) {
        unsigned int b = __float_as_uint(ssc[j]);
        if (b > T) gt++; else if (b == T) eq++;
    }
    s_gt[tid] = gt; s_eq[tid] = eq;
    __syncthreads();
    for (int off = 1; off < 1024; off <<= 1) {
        int vg = (tid >= off) ? s_gt[tid - off] : 0;
        int ve = (tid >= off) ? s_eq[tid - off] : 0;
        __syncthreads();
        s_gt[tid] += vg; s_eq[tid] += ve;
        __syncthreads();
    }
    int gt_base = s_gt[tid] - gt;
    int eq_base = s_eq[tid] - eq;
    int total_gt = s_gt[1023];
    int pg = gt_base, pe = eq_base;
    for (int j = j0; j < j1; j++) {
        unsigned int b = __float_as_uint(ssc[j]);
        if (b > T) { g_idx[pg++] = j; }
        else if (b == T) { if (pe < rem) g_idx[total_gt + pe] = j; pe++; }
    }
}

// ================= kernel 3: fused row-staged gather (x and W) ==============
__global__ void __launch_bounds__(512) gather_rows_kernel(const float* __restrict__ x,
                                                          const float* __restrict__ W) {
    extern __shared__ float srow[];   // DFF floats = 44032 B
    int b = blockIdx.x;
    const float* src;
    __half* dst;
    if (b < NMOD) { src = W + (long)b * DFF; dst = g_wsel + (long)b * KP; }
    else          { int t = b - NMOD; src = x + (long)t * DFF; dst = g_xsel + (long)t * KP; }

    uint32_t sbase = smem_u32(srow);
    #pragma unroll
    for (int i = 0; i < 6; i++) {
        int seg = threadIdx.x + i * 512;
        if (seg < DFF / 4) cp16(sbase + seg * 16, src + seg * 4);
    }
    cp_commit();
    cp_wait<0>();
    __syncthreads();

    const int2* idx2 = (const int2*)g_idx;
    __half2* d2 = (__half2*)dst;
    for (int p = threadIdx.x; p < KP / 2; p += 512) {
        int k0 = p * 2;
        float v0 = 0.f, v1 = 0.f;
        if (k0 < KSEL) {
            int2 ii = __ldg(&idx2[p]);
            v0 = srow[ii.x];
            if (k0 + 1 < KSEL) v1 = srow[ii.y];
        }
        d2[p] = __floats2half2_rn(v0, v1);
    }
}

// ================= kernel 4: HMMA f16 GEMM (R7-exact) =======================
__device__ __forceinline__ void load_stage(uint32_t stb, int chunk, int bmBase, int bnBase, int tid) {
    long c0 = (long)chunk * BK;          // in halves
    int row = tid >> 2, seg = tid & 3;   // row 0..63, seg 0..3 (16B segments)
    #pragma unroll
    for (int i = 0; i < 2; i++) {        // A: 128 token rows
        int r = row + i * 64;
        cp16(stb + (uint32_t)(r * RS * 2 + seg * 16),
             &g_xsel[(long)(bmBase + r) * KP + c0 + seg * 8]);
    }
    #pragma unroll
    for (int i = 0; i < 4; i++) {        // B: 256 d_model rows
        int r = row + i * 64;
        cp16(stb + (uint32_t)(A_BYTES + r * RS * 2 + seg * 16),
             &g_wsel[(long)(bnBase + r) * KP + c0 + seg * 8]);
    }
}

__device__ __forceinline__ void ldsm_half(uint32_t stb, int h,
                                          const uint32_t* a_off, const uint32_t* b_off,
                                          uint32_t (*A)[4], uint32_t (*B)[4]) {
    #pragma unroll
    for (int mt = 0; mt < 4; mt++)
        ldsm4(A[mt][0], A[mt][1], A[mt][2], A[mt][3], stb + a_off[mt] + h * 32);
    #pragma unroll
    for (int p = 0; p < 4; p++)
        ldsm4(B[p][0], B[p][1], B[p][2], B[p][3], stb + b_off[p] + h * 32);
}

__device__ __forceinline__ void mma_half(float (*acc)[8][4],
                                         uint32_t (*A)[4], uint32_t (*B)[4]) {
    #pragma unroll
    for (int mt = 0; mt < 4; mt++)
        #pragma unroll
        for (int nt = 0; nt < 8; nt++)
            mma16816(acc[mt][nt], A[mt], &B[nt >> 1][(nt & 1) * 2]);
}

__global__ void __launch_bounds__(256, 1) gemm_kernel(float* __restrict__ out) {
    extern __shared__ char smem[];
    uint32_t sb = smem_u32(smem);
    int tid = threadIdx.x, wid = tid >> 5, lane = tid & 31;
    int bmBase = blockIdx.y * BM, bnBase = blockIdx.x * BN;
    int wm = (wid >> 2) * 64;            // warp M base within tile
    int wn = (wid & 3) * 64;             // warp N base within tile

    int quad = lane >> 3, r8 = lane & 7;
    uint32_t a_off[4], b_off[4];
    #pragma unroll
    for (int mt = 0; mt < 4; mt++) {
        int row = wm + mt * 16 + (quad & 1) * 8 + r8;
        int col = (quad >> 1) * 8;
        a_off[mt] = (uint32_t)((row * RS + col) * 2);
    }
    #pragma unroll
    for (int p = 0; p < 4; p++) {
        int row = wn + p * 16 + (quad >> 1) * 8 + r8;
        int col = (quad & 1) * 8;
        b_off[p] = (uint32_t)(A_BYTES + (row * RS + col) * 2);
    }

    float acc[4][8][4];
    #pragma unroll
    for (int mt = 0; mt < 4; mt++)
        #pragma unroll
        for (int nt = 0; nt < 8; nt++)
            #pragma unroll
            for (int q = 0; q < 4; q++) acc[mt][nt][q] = 0.f;

    // preload NSTG-1 = 5 stages
    #pragma unroll
    for (int s = 0; s < NSTG - 1; s++) {
        load_stage(sb + s * STG_BYTES, s, bmBase, bnBase, tid);
        cp_commit();
    }

    uint32_t A0[4][4], B0[4][4], A1[4][4], B1[4][4];
    cp_wait<NSTG - 2>();
    __syncthreads();
    ldsm_half(sb, 0, a_off, b_off, A0, B0);      // chunk 0, half 0

    int st = 0;
    #pragma unroll 1
    for (int c = 0; c < NCHUNK; c++) {
        uint32_t stb = sb + st * STG_BYTES;
        // prefetch half 1 of current chunk before running half-0 MMAs
        ldsm_half(stb, 1, a_off, b_off, A1, B1);
        if (c + NSTG - 1 < NCHUNK) {
            int stn = st + (NSTG - 1); if (stn >= NSTG) stn -= NSTG;
            load_stage(sb + stn * STG_BYTES, c + NSTG - 1, bmBase, bnBase, tid);
        }
        cp_commit();
        mma_half(acc, A0, B0);

        cp_wait<NSTG - 2>();          // stage c+1 resident
        __syncthreads();
        int stn = st + 1; if (stn == NSTG) stn = 0;
        // prefetch half 0 of next chunk before running half-1 MMAs
        if (c + 1 < NCHUNK) ldsm_half(sb + stn * STG_BYTES, 0, a_off, b_off, A0, B0);
        mma_half(acc, A1, B1);
        st = stn;
    }

    // epilogue: direct f32 stores
    int rq = lane >> 2, cq = lane & 3;
    #pragma unroll
    for (int mt = 0; mt < 4; mt++) {
        #pragma unroll
        for (int nt = 0; nt < 8; nt++) {
            int m0 = bmBase + wm + mt * 16 + rq;
            int n0 = bnBase + wn + nt * 8 + cq * 2;
            float2* p0 = (float2*)(out + (long)m0 * NMOD + n0);
            float2* p1 = (float2*)(out + (long)(m0 + 8) * NMOD + n0);
            *p0 = make_float2(acc[mt][nt][0], acc[mt][nt][1]);
            *p1 = make_float2(acc[mt][nt][2], acc[mt][nt][3]);
        }
    }
}

// ================= launch =================
extern "C" void kernel_launch(void* const* d_in, const int* in_sizes, int n_in,
                              void* d_out, int out_size) {
    const float* x = (const float*)d_in[0];   // [1, 2048, 11008] f32
    const float* W = (const float*)d_in[1];   // [4096, 11008] f32
    float* out = (float*)d_out;               // [1, 2048, 4096] f32

    cudaFuncSetAttribute(gemm_kernel, cudaFuncAttributeMaxDynamicSharedMemorySize, GEMM_SMEM);
    cudaFuncSetAttribute(gather_rows_kernel, cudaFuncAttributeMaxDynamicSharedMemorySize, DFF * 4);
    cudaFuncSetAttribute(select_kernel, cudaFuncAttributeMaxDynamicSharedMemorySize, DFF * 4);

    score_partial_kernel<<<dim3(43, 16), 256>>>(x);
    reduce_scores_kernel<<<43, 256>>>();
    select_kernel<<<1, 1024, DFF * 4>>>();
    gather_rows_kernel<<<NMOD + MTOK, 512, DFF * 4>>>(x, W);
    gemm_kernel<<<dim3(NMOD / BN, MTOK / BM), 256, GEMM_SMEM>>>(out);
}